// round 3
// baseline (speedup 1.0000x reference)
#include <cuda_runtime.h>
#include <math.h>

#define MAXN 100000
#define HID 256
#define C 10
#define LH 128
#define G4 512
#define TSTEPS 12
#define HEADS 4
#define KP 16

__device__ float g_Wt1[LH*G4];
__device__ float g_Wt2[2*LH*G4];
__device__ float g_cW1t[HID*LH];
__device__ float g_probs[MAXN*C];
__device__ float g_x[MAXN*HEADS*C];
__device__ float g_as[MAXN*HEADS];
__device__ float g_ad[MAXN*HEADS];
__device__ float g_ssum[MAXN*HEADS];
__device__ float g_gout[MAXN*HEADS*C];
__device__ float g_deg[MAXN];
__device__ float g_nsum[MAXN*C];
__device__ float g_econf[MAXN];
__device__ float g_tconf[MAXN];
__device__ float g_maxp[MAXN];
__device__ float g_unc[MAXN];
__device__ int   g_lab[MAXN];

typedef unsigned long long u64;

__device__ __forceinline__ u64 fma2(u64 a,u64 b,u64 c){u64 d;asm("fma.rn.f32x2 %0,%1,%2,%3;":"=l"(d):"l"(a),"l"(b),"l"(c));return d;}
__device__ __forceinline__ u64 dup2(float x){u64 d;asm("mov.b64 %0,{%1,%1};":"=l"(d):"f"(x));return d;}
__device__ __forceinline__ float2 unp2(u64 v){float2 r;asm("mov.b64 {%0,%1},%2;":"=f"(r.x),"=f"(r.y):"l"(v));return r;}
__device__ __forceinline__ u64 pk2(float x,float y){u64 d;asm("mov.b64 %0,{%1,%2};":"=l"(d):"f"(x),"f"(y));return d;}
__device__ __forceinline__ void cpa16(float* s,const float* g){unsigned a=(unsigned)__cvta_generic_to_shared(s);asm volatile("cp.async.cg.shared.global [%0],[%1],16;"::"r"(a),"l"(g));}
__device__ __forceinline__ void cpcommit(){asm volatile("cp.async.commit_group;");}
__device__ __forceinline__ void cpwait(){asm volatile("cp.async.wait_group 0;");}
__device__ __forceinline__ float sigf(float x){return 1.f/(1.f+__expf(-x));}
__device__ __forceinline__ float tahf(float x){float e=__expf(2.f*x);return 1.f-2.f/(e+1.f);}

// ---------------- prep: transposes + zero accumulators ----------------
__global__ void k_prep(const float* __restrict__ w_hh0,const float* __restrict__ w_ih1,
                       const float* __restrict__ w_hh1,const float* __restrict__ cW1,int n){
  long i=(long)blockIdx.x*blockDim.x+threadIdx.x; long st=(long)gridDim.x*blockDim.x;
  for(long idx=i;idx<LH*G4;idx+=st){int k=(int)(idx/G4),g=(int)(idx%G4);g_Wt1[idx]=w_hh0[g*LH+k];}
  for(long idx=i;idx<2*LH*G4;idx+=st){int k=(int)(idx/G4),g=(int)(idx%G4);g_Wt2[idx]=(k<LH)?w_ih1[g*LH+k]:w_hh1[g*LH+k-LH];}
  for(long idx=i;idx<HID*LH;idx+=st){int k=(int)(idx/LH),o=(int)(idx%LH);g_cW1t[idx]=cW1[o*HID+k];}
  for(long idx=i;idx<(long)n*HEADS;idx+=st)g_ssum[idx]=0.f;
  for(long idx=i;idx<(long)n*HEADS*C;idx+=st)g_gout[idx]=0.f;
  for(long idx=i;idx<n;idx+=st)g_deg[idx]=0.f;
  for(long idx=i;idx<(long)n*C;idx+=st)g_nsum[idx]=0.f;
}

// ---------------- stage1: softmax/argmax/entropy + GAT projections ----------------
__global__ void k_stage1(const float* __restrict__ preds,const float* __restrict__ gW,
                         const float* __restrict__ gas,const float* __restrict__ gad,int n){
  __shared__ float sgW[C*HEADS*C],sas[HEADS*C],sad[HEADS*C];
  int t=threadIdx.x;
  for(int i=t;i<C*HEADS*C;i+=blockDim.x)sgW[i]=gW[i];
  if(t<HEADS*C){sas[t]=gas[t];sad[t]=gad[t];}
  __syncthreads();
  int i=blockIdx.x*blockDim.x+t; if(i>=n)return;
  float p[C];float m=-1e30f;
  #pragma unroll
  for(int c=0;c<C;c++){p[c]=preds[i*C+c];m=fmaxf(m,p[c]);}
  float s=0.f;
  #pragma unroll
  for(int c=0;c<C;c++){p[c]=expf(p[c]-m);s+=p[c];}
  float inv=1.f/s;int lab=0;float mp=-1.f,ent=0.f;
  #pragma unroll
  for(int c=0;c<C;c++){p[c]*=inv;if(p[c]>mp){mp=p[c];lab=c;}}
  #pragma unroll
  for(int c=0;c<C;c++){ent-=p[c]*logf(p[c]+1e-8f);g_probs[i*C+c]=p[c];}
  g_lab[i]=lab;g_maxp[i]=mp;g_unc[i]=ent/2.302585093f;
  float xv[HEADS*C];
  #pragma unroll
  for(int hc=0;hc<HEADS*C;hc++){float a=0.f;
    #pragma unroll
    for(int c=0;c<C;c++)a+=p[c]*sgW[c*(HEADS*C)+hc];
    xv[hc]=a;g_x[(long)i*(HEADS*C)+hc]=a;}
  #pragma unroll
  for(int h=0;h<HEADS;h++){float a=0.f,b=0.f;
    #pragma unroll
    for(int c=0;c<C;c++){a+=xv[h*C+c]*sas[h*C+c];b+=xv[h*C+c]*sad[h*C+c];}
    g_as[i*HEADS+h]=a;g_ad[i*HEADS+h]=b;}
}

// ---------------- confidence net: sigmoid(relu(emb@W1^T+b1)@W2^T+b2) ----------------
__global__ void __launch_bounds__(256) k_conf(const float* __restrict__ emb,const float* __restrict__ cb1,
                                              const float* __restrict__ cW2,const float* __restrict__ cb2,int n){
  extern __shared__ float sm[];
  float* sW=sm;          // 32768 floats (W1 transposed [k][128])
  float* sE=sm+32768;    // 8192 floats (emb [32][256])
  int t=threadIdx.x;int node0=blockIdx.x*32;
  for(int idx=t;idx<32768;idx+=256)sW[idx]=g_cW1t[idx];
  for(int idx=t;idx<8192;idx+=256){int nl=idx>>8,k=idx&255;sE[idx]=(node0+nl<n)?emb[(long)(node0+nl)*HID+k]:0.f;}
  __syncthreads();
  int j4=t&31,r=t>>5;
  float acc[4][4];
  #pragma unroll
  for(int a=0;a<4;a++){acc[a][0]=0;acc[a][1]=0;acc[a][2]=0;acc[a][3]=0;}
  for(int k=0;k<HID;k++){
    float4 w=*(const float4*)&sW[k*LH+j4*4];
    #pragma unroll
    for(int i=0;i<4;i++){
      float e=sE[(r*4+i)*HID+k];
      acc[i][0]=fmaf(e,w.x,acc[i][0]);acc[i][1]=fmaf(e,w.y,acc[i][1]);
      acc[i][2]=fmaf(e,w.z,acc[i][2]);acc[i][3]=fmaf(e,w.w,acc[i][3]);}}
  float b1[4],w2[4];
  #pragma unroll
  for(int cc=0;cc<4;cc++){b1[cc]=cb1[j4*4+cc];w2[cc]=cW2[j4*4+cc];}
  float b2=cb2[0];
  #pragma unroll
  for(int i=0;i<4;i++){
    float pi=0.f;
    #pragma unroll
    for(int cc=0;cc<4;cc++){float h=fmaxf(acc[i][cc]+b1[cc],0.f);pi=fmaf(h,w2[cc],pi);}
    #pragma unroll
    for(int off=16;off>0;off>>=1)pi+=__shfl_xor_sync(0xffffffffu,pi,off);
    if(j4==0){int node=node0+r*4+i;if(node<n)g_econf[node]=sigf(pi+b2);}
  }
}

// ---------------- fused 2-layer LSTM, 16 nodes/CTA, f32x2 packed math ----------------
__global__ void __launch_bounds__(256) k_lstm(const float* __restrict__ preds,const float* __restrict__ w_ih0,
    const float* __restrict__ b_ih0,const float* __restrict__ b_hh0,
    const float* __restrict__ b_ih1,const float* __restrict__ b_hh1,int n){
  extern __shared__ float sm[];
  float* panel=sm;        // 16384: 2 x [16][512]
  float* sXW=sm+16384;    // 8192:  [8 pairs][512] f32x2
  float* sH1=sm+24576;    // 3072:  [128][12] f32x2 (pad 12)
  float* sH2=sm+27648;    // 3072
  float* sB2=sm+30720;    // 512
  float* sP =sm+31232;    // 160: [8 pairs][10] f32x2
  float* sRed=sm+31392;   // 16
  int t=threadIdx.x,j=t&127,ty=t>>7;
  int node0=blockIdx.x*16;
  for(int idx=t;idx<80;idx+=256){int pr=idx/10,c=idx%10;int n0=node0+pr*2;
    float x=(n0<n)?preds[n0*C+c]:0.f;float y=(n0+1<n)?preds[(n0+1)*C+c]:0.f;
    *(u64*)&sP[idx*2]=pk2(x,y);}
  for(int idx=t;idx<512;idx+=256)sB2[idx]=b_ih1[idx]+b_hh1[idx];
  for(int idx=t;idx<3072;idx+=256){sH1[idx]=0.f;sH2[idx]=0.f;}
  if(t<16)sRed[t]=0.f;
  __syncthreads();
  // xW_ih0 + biases, per node, once
  #pragma unroll
  for(int gi=0;gi<4;gi++){
    int g=gi*128+j;
    float wv[10];
    #pragma unroll
    for(int c=0;c<10;c++)wv[c]=w_ih0[g*10+c];
    float b0=b_ih0[g]+b_hh0[g];
    #pragma unroll
    for(int p=0;p<4;p++){
      int pair=ty*4+p;
      u64 a=dup2(b0);
      #pragma unroll
      for(int c=0;c<10;c++)a=fma2(*(const u64*)&sP[(pair*10+c)*2],dup2(wv[c]),a);
      *(u64*)&sXW[(pair*512+g)*2]=a;}}
  __syncthreads();
  u64 acc[4][4];
  float c1[8],c2[8],s1[8],s2[8];
  #pragma unroll
  for(int i=0;i<8;i++){c1[i]=0.f;c2[i]=0.f;s1[i]=0.f;s2[i]=0.f;}
  // prologue: issue panel 0
  {
    #pragma unroll
    for(int i=0;i<8;i++){int u=t+i*256;cpa16(panel+u*4,g_Wt1+u*4);}
    cpcommit();
  }
  for(int tt=0;tt<TSTEPS;tt++){
    // ---- layer 1: gates = sXW + W_hh0 @ h1 ----
    #pragma unroll
    for(int gi=0;gi<4;gi++)
      #pragma unroll
      for(int p=0;p<4;p++)acc[gi][p]=*(const u64*)&sXW[((ty*4+p)*512+gi*128+j)*2];
    for(int pp=0;pp<8;pp++){
      cpwait();__syncthreads();
      {int nx=(pp+1)%24;const float* src=(nx<8)?(g_Wt1+nx*KP*G4):(g_Wt2+(nx-8)*KP*G4);
       float* dst=panel+(nx&1)*8192;
       #pragma unroll
       for(int i=0;i<8;i++){int u=t+i*256;cpa16(dst+u*4,src+u*4);}
       cpcommit();}
      const float* sp=panel+(pp&1)*8192;
      int kb=pp*KP;
      #pragma unroll 4
      for(int kk=0;kk<KP;kk++){
        int k=kb+kk;
        const u64* hp=(const u64*)&sH1[(k*12+ty*4)*2];
        u64 h0=hp[0],h1=hp[1],h2v=hp[2],h3=hp[3];
        #pragma unroll
        for(int gi=0;gi<4;gi++){
          u64 w=dup2(sp[kk*G4+gi*128+j]);
          acc[gi][0]=fma2(h0,w,acc[gi][0]);
          acc[gi][1]=fma2(h1,w,acc[gi][1]);
          acc[gi][2]=fma2(h2v,w,acc[gi][2]);
          acc[gi][3]=fma2(h3,w,acc[gi][3]);}}
    }
    __syncthreads();
    #pragma unroll
    for(int p=0;p<4;p++){
      float2 iv=unp2(acc[0][p]),fv=unp2(acc[1][p]),gv=unp2(acc[2][p]),ov=unp2(acc[3][p]);
      float cx=sigf(fv.x)*c1[p*2]+sigf(iv.x)*tahf(gv.x);
      float cy=sigf(fv.y)*c1[p*2+1]+sigf(iv.y)*tahf(gv.y);
      c1[p*2]=cx;c1[p*2+1]=cy;
      float hx=sigf(ov.x)*tahf(cx),hy=sigf(ov.y)*tahf(cy);
      int o=(j*12+ty*4+p)*2;sH1[o]=hx;sH1[o+1]=hy;}
    // ---- layer 2: gates = b + W_ih1 @ h1 + W_hh1 @ h2 ----
    #pragma unroll
    for(int gi=0;gi<4;gi++){u64 b=dup2(sB2[gi*128+j]);
      #pragma unroll
      for(int p=0;p<4;p++)acc[gi][p]=b;}
    for(int pp=8;pp<24;pp++){
      cpwait();__syncthreads();
      {int nx=(pp+1)%24;const float* src=(nx<8)?(g_Wt1+nx*KP*G4):(g_Wt2+(nx-8)*KP*G4);
       float* dst=panel+(nx&1)*8192;
       #pragma unroll
       for(int i=0;i<8;i++){int u=t+i*256;cpa16(dst+u*4,src+u*4);}
       cpcommit();}
      const float* sp=panel+(pp&1)*8192;
      const float* hs=(pp<16)?sH1:sH2;
      int kb=((pp-8)*KP)&127;
      #pragma unroll 4
      for(int kk=0;kk<KP;kk++){
        int k=kb+kk;
        const u64* hp=(const u64*)&hs[(k*12+ty*4)*2];
        u64 h0=hp[0],h1=hp[1],h2v=hp[2],h3=hp[3];
        #pragma unroll
        for(int gi=0;gi<4;gi++){
          u64 w=dup2(sp[kk*G4+gi*128+j]);
          acc[gi][0]=fma2(h0,w,acc[gi][0]);
          acc[gi][1]=fma2(h1,w,acc[gi][1]);
          acc[gi][2]=fma2(h2v,w,acc[gi][2]);
          acc[gi][3]=fma2(h3,w,acc[gi][3]);}}
    }
    __syncthreads();
    #pragma unroll
    for(int p=0;p<4;p++){
      float2 iv=unp2(acc[0][p]),fv=unp2(acc[1][p]),gv=unp2(acc[2][p]),ov=unp2(acc[3][p]);
      float cx=sigf(fv.x)*c2[p*2]+sigf(iv.x)*tahf(gv.x);
      float cy=sigf(fv.y)*c2[p*2+1]+sigf(iv.y)*tahf(gv.y);
      c2[p*2]=cx;c2[p*2+1]=cy;
      float hx=sigf(ov.x)*tahf(cx),hy=sigf(ov.y)*tahf(cy);
      int o=(j*12+ty*4+p)*2;sH2[o]=hx;sH2[o+1]=hy;
      s1[p*2]+=hx;s1[p*2+1]+=hy;s2[p*2]+=hx*hx;s2[p*2+1]+=hy*hy;}
  }
  __syncthreads();
  #pragma unroll
  for(int p=0;p<4;p++){
    #pragma unroll
    for(int cc=0;cc<2;cc++){
      float a=s1[p*2+cc],b=s2[p*2+cc];
      float var=(b-a*a*(1.f/12.f))*(1.f/11.f);
      atomicAdd(&sRed[(ty*4+p)*2+cc],var);}}
  __syncthreads();
  if(t<16){int node=node0+t;if(node<n)g_tconf[node]=1.f/(1.f+sRed[t]*(1.f/128.f));}
}

// ---------------- single-pass GAT edge scatter + agreement scatter ----------------
__global__ void k_edge(const int* __restrict__ ei,long E,int n){
  long e=(long)blockIdx.x*blockDim.x+threadIdx.x;
  long tot=E+n;
  if(e>=tot)return;
  int s,d;
  if(e<E){s=ei[e];d=ei[E+e];}else{s=(int)(e-E);d=s;}
  float ex[HEADS];
  #pragma unroll
  for(int h=0;h<HEADS;h++){
    float v=g_as[s*HEADS+h]+g_ad[d*HEADS+h];
    v=(v>0.f)?v:0.2f*v;
    ex[h]=__expf(v);
    atomicAdd(&g_ssum[d*HEADS+h],ex[h]);}
  const float* xs=&g_x[(long)s*HEADS*C];
  float* go=&g_gout[(long)d*HEADS*C];
  #pragma unroll
  for(int h=0;h<HEADS;h++)
    #pragma unroll
    for(int c=0;c<C;c++)
      atomicAdd(&go[h*C+c],ex[h]*xs[h*C+c]);
  atomicAdd(&g_deg[s],1.f);
  atomicAdd(&g_nsum[d*C+g_lab[s]],1.f);
}

// ---------------- finalize: gout normalize, cosine, combined, mask, outputs ----------------
__global__ void k_final(const float* __restrict__ gb,float* __restrict__ out,int n){
  int i=blockIdx.x*blockDim.x+threadIdx.x;if(i>=n)return;
  float p[C],go[C];
  #pragma unroll
  for(int c=0;c<C;c++){p[c]=g_probs[i*C+c];go[c]=0.f;}
  #pragma unroll
  for(int h=0;h<HEADS;h++){
    float sh=g_ssum[i*HEADS+h]+1e-16f;float inv=1.f/sh;
    #pragma unroll
    for(int c=0;c<C;c++)go[c]+=g_gout[(long)i*HEADS*C+h*C+c]*inv;}
  float num=0.f,np=0.f,ng=0.f;
  #pragma unroll
  for(int c=0;c<C;c++){go[c]=go[c]*0.25f+gb[c];num+=p[c]*go[c];np+=p[c]*p[c];ng+=go[c]*go[c];}
  float den=fmaxf(sqrtf(np)*sqrtf(ng),1e-8f);
  float gconf=(num/den+1.f)*0.5f;
  float comb=0.4f*g_maxp[i]+0.2f*g_econf[i]+0.2f*g_tconf[i]+0.2f*gconf;
  int lab=g_lab[i];
  float navg=g_nsum[i*C+lab]/(g_deg[i]+1e-8f);
  float mask=((comb>0.85f)&&(navg>=0.6f))?1.f:0.f;
  out[i]=(float)lab;
  out[n+i]=comb;
  out[2*n+i]=mask;
  out[3*n+i]=g_maxp[i];
  out[4*n+i]=g_econf[i];
  out[5*n+i]=g_tconf[i];
  out[6*n+i]=gconf;
  out[7*n+i]=g_unc[i];
}

extern "C" void kernel_launch(void* const* d_in,const int* in_sizes,int n_in,
                              void* d_out,int out_size){
  const float* emb  =(const float*)d_in[0];
  const float* preds=(const float*)d_in[1];
  const int*   ei   =(const int*)  d_in[3];
  const float* cW1  =(const float*)d_in[4];
  const float* cb1  =(const float*)d_in[5];
  const float* cW2  =(const float*)d_in[6];
  const float* cb2  =(const float*)d_in[7];
  const float* w_ih0=(const float*)d_in[8];
  const float* w_hh0=(const float*)d_in[9];
  const float* b_ih0=(const float*)d_in[10];
  const float* b_hh0=(const float*)d_in[11];
  const float* w_ih1=(const float*)d_in[12];
  const float* w_hh1=(const float*)d_in[13];
  const float* b_ih1=(const float*)d_in[14];
  const float* b_hh1=(const float*)d_in[15];
  const float* gW   =(const float*)d_in[16];
  const float* gas  =(const float*)d_in[17];
  const float* gad  =(const float*)d_in[18];
  const float* gb   =(const float*)d_in[19];
  int n=in_sizes[1]/C;
  long E=in_sizes[3]/2;

  cudaFuncSetAttribute(k_lstm,cudaFuncAttributeMaxDynamicSharedMemorySize,31408*4);
  cudaFuncSetAttribute(k_conf,cudaFuncAttributeMaxDynamicSharedMemorySize,40960*4);

  k_prep<<<2048,256>>>(w_hh0,w_ih1,w_hh1,cW1,n);
  k_stage1<<<(n+255)/256,256>>>(preds,gW,gas,gad,n);
  k_conf<<<(n+31)/32,256,40960*4>>>(emb,cb1,cW2,cb2,n);
  k_lstm<<<(n+15)/16,256,31408*4>>>(preds,w_ih0,b_ih0,b_hh0,b_ih1,b_hh1,n);
  long tot=E+n;
  k_edge<<<(int)((tot+255)/256),256>>>(ei,E,n);
  k_final<<<(n+255)/256,256>>>(gb,(float*)d_out,n);
}

// round 4
// speedup vs baseline: 2.1005x; 2.1005x over previous
#include <cuda_runtime.h>
#include <math.h>

#define MAXN 100000
#define HID 256
#define C 10
#define LH 128
#define G4 512
#define TSTEPS 12
#define HEADS 4
#define KP 8           // k-steps per panel
#define PANEL_F 4096   // 512 gates * 8 k = floats per panel
#define NPAN 48        // 16 (layer1) + 32 (layer2)

__device__ float g_Wt1[LH*G4];      // 16 panels, layout [pp][half][g][4]
__device__ float g_Wt2[2*LH*G4];    // 32 panels, layout [pp][half][g][4]
__device__ float g_cW1t[HID*LH];
__device__ float g_probs[MAXN*C];
__device__ float g_x[MAXN*HEADS*C];
__device__ float g_as[MAXN*HEADS];
__device__ float g_ad[MAXN*HEADS];
__device__ float g_ssum[MAXN*HEADS];
__device__ float g_gout[MAXN*HEADS*C];
__device__ float g_deg[MAXN];
__device__ float g_nsum[MAXN*C];
__device__ float g_econf[MAXN];
__device__ float g_tconf[MAXN];
__device__ float g_maxp[MAXN];
__device__ float g_unc[MAXN];
__device__ int   g_lab[MAXN];

typedef unsigned long long u64;

__device__ __forceinline__ u64 fma2(u64 a,u64 b,u64 c){u64 d;asm("fma.rn.f32x2 %0,%1,%2,%3;":"=l"(d):"l"(a),"l"(b),"l"(c));return d;}
__device__ __forceinline__ u64 dup2(float x){u64 d;asm("mov.b64 %0,{%1,%1};":"=l"(d):"f"(x));return d;}
__device__ __forceinline__ float2 unp2(u64 v){float2 r;asm("mov.b64 {%0,%1},%2;":"=f"(r.x),"=f"(r.y):"l"(v));return r;}
__device__ __forceinline__ u64 pk2(float x,float y){u64 d;asm("mov.b64 %0,{%1,%2};":"=l"(d):"f"(x),"f"(y));return d;}
__device__ __forceinline__ void cpa16(float* s,const float* g){unsigned a=(unsigned)__cvta_generic_to_shared(s);asm volatile("cp.async.cg.shared.global [%0],[%1],16;"::"r"(a),"l"(g));}
__device__ __forceinline__ void cpcommit(){asm volatile("cp.async.commit_group;");}
__device__ __forceinline__ void cpwait(){asm volatile("cp.async.wait_group 0;");}
__device__ __forceinline__ float sigf(float x){return 1.f/(1.f+__expf(-x));}
__device__ __forceinline__ float tahf(float x){float e=__expf(2.f*x);return 1.f-2.f/(e+1.f);}

// ---------------- prep: panel-transposed weights + zero accumulators ----------------
__global__ void k_prep(const float* __restrict__ w_hh0,const float* __restrict__ w_ih1,
                       const float* __restrict__ w_hh1,const float* __restrict__ cW1,int n){
  long i=(long)blockIdx.x*blockDim.x+threadIdx.x; long st=(long)gridDim.x*blockDim.x;
  // layout: idx = ((pp*2+half)*512 + g)*4 + m ; k = pp*8 + half*4 + m
  for(long idx=i;idx<LH*G4;idx+=st){
    int m=(int)(idx&3); int g=(int)((idx>>2)&511); int ph=(int)(idx>>13);
    int k=(ph>>1)*8 + (ph&1)*4 + m;
    g_Wt1[idx]=w_hh0[g*LH+k];
  }
  for(long idx=i;idx<2*LH*G4;idx+=st){
    int m=(int)(idx&3); int g=(int)((idx>>2)&511); int ph=(int)(idx>>13);
    int k=(ph>>1)*8 + (ph&1)*4 + m;
    g_Wt2[idx]=(k<LH)?w_ih1[g*LH+k]:w_hh1[g*LH+k-LH];
  }
  for(long idx=i;idx<HID*LH;idx+=st){int k=(int)(idx/LH),o=(int)(idx%LH);g_cW1t[idx]=cW1[o*HID+k];}
  for(long idx=i;idx<(long)n*HEADS;idx+=st)g_ssum[idx]=0.f;
  for(long idx=i;idx<(long)n*HEADS*C;idx+=st)g_gout[idx]=0.f;
  for(long idx=i;idx<n;idx+=st)g_deg[idx]=0.f;
  for(long idx=i;idx<(long)n*C;idx+=st)g_nsum[idx]=0.f;
}

// ---------------- stage1: softmax/argmax/entropy + GAT projections ----------------
__global__ void k_stage1(const float* __restrict__ preds,const float* __restrict__ gW,
                         const float* __restrict__ gas,const float* __restrict__ gad,int n){
  __shared__ float sgW[C*HEADS*C],sas[HEADS*C],sad[HEADS*C];
  int t=threadIdx.x;
  for(int i=t;i<C*HEADS*C;i+=blockDim.x)sgW[i]=gW[i];
  if(t<HEADS*C){sas[t]=gas[t];sad[t]=gad[t];}
  __syncthreads();
  int i=blockIdx.x*blockDim.x+t; if(i>=n)return;
  float p[C];float m=-1e30f;
  #pragma unroll
  for(int c=0;c<C;c++){p[c]=preds[i*C+c];m=fmaxf(m,p[c]);}
  float s=0.f;
  #pragma unroll
  for(int c=0;c<C;c++){p[c]=expf(p[c]-m);s+=p[c];}
  float inv=1.f/s;int lab=0;float mp=-1.f,ent=0.f;
  #pragma unroll
  for(int c=0;c<C;c++){p[c]*=inv;if(p[c]>mp){mp=p[c];lab=c;}}
  #pragma unroll
  for(int c=0;c<C;c++){ent-=p[c]*logf(p[c]+1e-8f);g_probs[i*C+c]=p[c];}
  g_lab[i]=lab;g_maxp[i]=mp;g_unc[i]=ent/2.302585093f;
  float xv[HEADS*C];
  #pragma unroll
  for(int hc=0;hc<HEADS*C;hc++){float a=0.f;
    #pragma unroll
    for(int c=0;c<C;c++)a+=p[c]*sgW[c*(HEADS*C)+hc];
    xv[hc]=a;g_x[(long)i*(HEADS*C)+hc]=a;}
  #pragma unroll
  for(int h=0;h<HEADS;h++){float a=0.f,b=0.f;
    #pragma unroll
    for(int c=0;c<C;c++){a+=xv[h*C+c]*sas[h*C+c];b+=xv[h*C+c]*sad[h*C+c];}
    g_as[i*HEADS+h]=a;g_ad[i*HEADS+h]=b;}
}

// ---------------- confidence net: sigmoid(relu(emb@W1^T+b1)@W2^T+b2) ----------------
__global__ void __launch_bounds__(256) k_conf(const float* __restrict__ emb,const float* __restrict__ cb1,
                                              const float* __restrict__ cW2,const float* __restrict__ cb2,int n){
  extern __shared__ float sm[];
  float* sW=sm;          // 32768 floats (W1 transposed [k][128])
  float* sE=sm+32768;    // 8192 floats (emb [32][256])
  int t=threadIdx.x;int node0=blockIdx.x*32;
  for(int idx=t;idx<32768;idx+=256)sW[idx]=g_cW1t[idx];
  for(int idx=t;idx<8192;idx+=256){int nl=idx>>8,k=idx&255;sE[idx]=(node0+nl<n)?emb[(long)(node0+nl)*HID+k]:0.f;}
  __syncthreads();
  int j4=t&31,r=t>>5;
  float acc[4][4];
  #pragma unroll
  for(int a=0;a<4;a++){acc[a][0]=0;acc[a][1]=0;acc[a][2]=0;acc[a][3]=0;}
  for(int k=0;k<HID;k++){
    float4 w=*(const float4*)&sW[k*LH+j4*4];
    #pragma unroll
    for(int i=0;i<4;i++){
      float e=sE[(r*4+i)*HID+k];
      acc[i][0]=fmaf(e,w.x,acc[i][0]);acc[i][1]=fmaf(e,w.y,acc[i][1]);
      acc[i][2]=fmaf(e,w.z,acc[i][2]);acc[i][3]=fmaf(e,w.w,acc[i][3]);}}
  float b1[4],w2[4];
  #pragma unroll
  for(int cc=0;cc<4;cc++){b1[cc]=cb1[j4*4+cc];w2[cc]=cW2[j4*4+cc];}
  float b2=cb2[0];
  #pragma unroll
  for(int i=0;i<4;i++){
    float pi=0.f;
    #pragma unroll
    for(int cc=0;cc<4;cc++){float h=fmaxf(acc[i][cc]+b1[cc],0.f);pi=fmaf(h,w2[cc],pi);}
    #pragma unroll
    for(int off=16;off>0;off>>=1)pi+=__shfl_xor_sync(0xffffffffu,pi,off);
    if(j4==0){int node=node0+r*4+i;if(node<n)g_econf[node]=sigf(pi+b2);}
  }
}

// ---------------- fused 2-layer LSTM, 16 nodes/CTA, f32x2, 2 CTAs/SM ----------------
__device__ __forceinline__ const float* psrc(int q){
  return (q<16) ? (g_Wt1 + (long)q*PANEL_F) : (g_Wt2 + (long)(q-16)*PANEL_F);
}

__global__ void __launch_bounds__(256,2) k_lstm(const float* __restrict__ preds,const float* __restrict__ w_ih0,
    const float* __restrict__ b_ih0,const float* __restrict__ b_hh0,
    const float* __restrict__ b_ih1,const float* __restrict__ b_hh1,int n){
  extern __shared__ float sm[];
  float* panel=sm;          // 8192: 2 x 4096
  float* sXW=sm+8192;       // 8192: [8 pairs][512] f32x2
  float* sH1=sm+16384;      // 3072: [128][12] f32x2
  float* sH2=sm+19456;      // 3072
  float* sB2=sm+22528;      // 512
  float* sP =sm+23040;      // 160
  float* sRed=sm+23200;     // 16
  int t=threadIdx.x,j=t&127,ty=t>>7;
  int node0=blockIdx.x*16;
  for(int idx=t;idx<80;idx+=256){int pr=idx/10,c=idx%10;int n0=node0+pr*2;
    float x=(n0<n)?preds[n0*C+c]:0.f;float y=(n0+1<n)?preds[(n0+1)*C+c]:0.f;
    *(u64*)&sP[idx*2]=pk2(x,y);}
  for(int idx=t;idx<512;idx+=256)sB2[idx]=b_ih1[idx]+b_hh1[idx];
  for(int idx=t;idx<3072;idx+=256){sH1[idx]=0.f;sH2[idx]=0.f;}
  if(t<16)sRed[t]=0.f;
  __syncthreads();
  // xW_ih0 + biases, per node, once
  #pragma unroll
  for(int gi=0;gi<4;gi++){
    int g=gi*128+j;
    float wv[10];
    #pragma unroll
    for(int c=0;c<10;c++)wv[c]=w_ih0[g*10+c];
    float b0=b_ih0[g]+b_hh0[g];
    #pragma unroll
    for(int p=0;p<4;p++){
      int pair=ty*4+p;
      u64 a=dup2(b0);
      #pragma unroll
      for(int c=0;c<10;c++)a=fma2(*(const u64*)&sP[(pair*10+c)*2],dup2(wv[c]),a);
      *(u64*)&sXW[(pair*512+g)*2]=a;}}
  __syncthreads();

  u64 acc[4][4];
  float c1[8],c2[8],s1[8],s2[8];
  #pragma unroll
  for(int i=0;i<8;i++){c1[i]=0.f;c2[i]=0.f;s1[i]=0.f;s2[i]=0.f;}

  // prologue: prefetch panel 0
  {
    const float* src=psrc(0);
    #pragma unroll
    for(int i=0;i<4;i++){int u=t+i*256;cpa16(panel+u*4,src+u*4);}
    cpcommit();
  }

  for(int tt=0;tt<TSTEPS;tt++){
    // ---- layer 1 ----
    #pragma unroll
    for(int gi=0;gi<4;gi++)
      #pragma unroll
      for(int p=0;p<4;p++)acc[gi][p]=*(const u64*)&sXW[((ty*4+p)*512+gi*128+j)*2];
    for(int q=0;q<16;q++){
      cpwait();__syncthreads();
      {int nx=q+1;const float* src=psrc(nx);float* dst=panel+(nx&1)*PANEL_F;
       #pragma unroll
       for(int i=0;i<4;i++){int u=t+i*256;cpa16(dst+u*4,src+u*4);}
       cpcommit();}
      const float* sp=panel+(q&1)*PANEL_F;
      int kb=q*KP;
      #pragma unroll
      for(int half=0;half<2;half++){
        float4 w0=*(const float4*)&sp[(half*512+  0+j)*4];
        float4 w1=*(const float4*)&sp[(half*512+128+j)*4];
        float4 w2=*(const float4*)&sp[(half*512+256+j)*4];
        float4 w3=*(const float4*)&sp[(half*512+384+j)*4];
        const float* wp0=(const float*)&w0;const float* wp1=(const float*)&w1;
        const float* wp2=(const float*)&w2;const float* wp3=(const float*)&w3;
        #pragma unroll
        for(int kx=0;kx<4;kx++){
          int k=kb+half*4+kx;
          const u64* hp=(const u64*)&sH1[(k*12+ty*4)*2];
          u64 h0=hp[0],h1=hp[1],h2v=hp[2],h3=hp[3];
          u64 d0=dup2(wp0[kx]),d1=dup2(wp1[kx]),d2=dup2(wp2[kx]),d3=dup2(wp3[kx]);
          acc[0][0]=fma2(h0,d0,acc[0][0]);acc[0][1]=fma2(h1,d0,acc[0][1]);
          acc[0][2]=fma2(h2v,d0,acc[0][2]);acc[0][3]=fma2(h3,d0,acc[0][3]);
          acc[1][0]=fma2(h0,d1,acc[1][0]);acc[1][1]=fma2(h1,d1,acc[1][1]);
          acc[1][2]=fma2(h2v,d1,acc[1][2]);acc[1][3]=fma2(h3,d1,acc[1][3]);
          acc[2][0]=fma2(h0,d2,acc[2][0]);acc[2][1]=fma2(h1,d2,acc[2][1]);
          acc[2][2]=fma2(h2v,d2,acc[2][2]);acc[2][3]=fma2(h3,d2,acc[2][3]);
          acc[3][0]=fma2(h0,d3,acc[3][0]);acc[3][1]=fma2(h1,d3,acc[3][1]);
          acc[3][2]=fma2(h2v,d3,acc[3][2]);acc[3][3]=fma2(h3,d3,acc[3][3]);}}
    }
    __syncthreads();
    #pragma unroll
    for(int p=0;p<4;p++){
      float2 iv=unp2(acc[0][p]),fv=unp2(acc[1][p]),gv=unp2(acc[2][p]),ov=unp2(acc[3][p]);
      float cx=sigf(fv.x)*c1[p*2]+sigf(iv.x)*tahf(gv.x);
      float cy=sigf(fv.y)*c1[p*2+1]+sigf(iv.y)*tahf(gv.y);
      c1[p*2]=cx;c1[p*2+1]=cy;
      float hx=sigf(ov.x)*tahf(cx),hy=sigf(ov.y)*tahf(cy);
      int o=(j*12+ty*4+p)*2;sH1[o]=hx;sH1[o+1]=hy;}
    // ---- layer 2 ----
    #pragma unroll
    for(int gi=0;gi<4;gi++){u64 b=dup2(sB2[gi*128+j]);
      #pragma unroll
      for(int p=0;p<4;p++)acc[gi][p]=b;}
    for(int q=16;q<48;q++){
      cpwait();__syncthreads();
      {int nx=(q+1==48)?0:q+1;const float* src=psrc(nx);float* dst=panel+(nx&1)*PANEL_F;
       #pragma unroll
       for(int i=0;i<4;i++){int u=t+i*256;cpa16(dst+u*4,src+u*4);}
       cpcommit();}
      const float* sp=panel+(q&1)*PANEL_F;
      const float* hs=(q<32)?sH1:sH2;
      int kb=((q-16)*KP)&127;
      #pragma unroll
      for(int half=0;half<2;half++){
        float4 w0=*(const float4*)&sp[(half*512+  0+j)*4];
        float4 w1=*(const float4*)&sp[(half*512+128+j)*4];
        float4 w2=*(const float4*)&sp[(half*512+256+j)*4];
        float4 w3=*(const float4*)&sp[(half*512+384+j)*4];
        const float* wp0=(const float*)&w0;const float* wp1=(const float*)&w1;
        const float* wp2=(const float*)&w2;const float* wp3=(const float*)&w3;
        #pragma unroll
        for(int kx=0;kx<4;kx++){
          int k=kb+half*4+kx;
          const u64* hp=(const u64*)&hs[(k*12+ty*4)*2];
          u64 h0=hp[0],h1=hp[1],h2v=hp[2],h3=hp[3];
          u64 d0=dup2(wp0[kx]),d1=dup2(wp1[kx]),d2=dup2(wp2[kx]),d3=dup2(wp3[kx]);
          acc[0][0]=fma2(h0,d0,acc[0][0]);acc[0][1]=fma2(h1,d0,acc[0][1]);
          acc[0][2]=fma2(h2v,d0,acc[0][2]);acc[0][3]=fma2(h3,d0,acc[0][3]);
          acc[1][0]=fma2(h0,d1,acc[1][0]);acc[1][1]=fma2(h1,d1,acc[1][1]);
          acc[1][2]=fma2(h2v,d1,acc[1][2]);acc[1][3]=fma2(h3,d1,acc[1][3]);
          acc[2][0]=fma2(h0,d2,acc[2][0]);acc[2][1]=fma2(h1,d2,acc[2][1]);
          acc[2][2]=fma2(h2v,d2,acc[2][2]);acc[2][3]=fma2(h3,d2,acc[2][3]);
          acc[3][0]=fma2(h0,d3,acc[3][0]);acc[3][1]=fma2(h1,d3,acc[3][1]);
          acc[3][2]=fma2(h2v,d3,acc[3][2]);acc[3][3]=fma2(h3,d3,acc[3][3]);}}
    }
    __syncthreads();
    #pragma unroll
    for(int p=0;p<4;p++){
      float2 iv=unp2(acc[0][p]),fv=unp2(acc[1][p]),gv=unp2(acc[2][p]),ov=unp2(acc[3][p]);
      float cx=sigf(fv.x)*c2[p*2]+sigf(iv.x)*tahf(gv.x);
      float cy=sigf(fv.y)*c2[p*2+1]+sigf(iv.y)*tahf(gv.y);
      c2[p*2]=cx;c2[p*2+1]=cy;
      float hx=sigf(ov.x)*tahf(cx),hy=sigf(ov.y)*tahf(cy);
      int o=(j*12+ty*4+p)*2;sH2[o]=hx;sH2[o+1]=hy;
      s1[p*2]+=hx;s1[p*2+1]+=hy;s2[p*2]+=hx*hx;s2[p*2+1]+=hy*hy;}
  }
  __syncthreads();
  #pragma unroll
  for(int p=0;p<4;p++){
    #pragma unroll
    for(int cc=0;cc<2;cc++){
      float a=s1[p*2+cc],b=s2[p*2+cc];
      float var=(b-a*a*(1.f/12.f))*(1.f/11.f);
      atomicAdd(&sRed[(ty*4+p)*2+cc],var);}}
  __syncthreads();
  if(t<16){int node=node0+t;if(node<n)g_tconf[node]=1.f/(1.f+sRed[t]*(1.f/128.f));}
}

// ---------------- single-pass GAT edge scatter + agreement scatter ----------------
__global__ void k_edge(const int* __restrict__ ei,long E,int n){
  long e=(long)blockIdx.x*blockDim.x+threadIdx.x;
  long tot=E+n;
  if(e>=tot)return;
  int s,d;
  if(e<E){s=ei[e];d=ei[E+e];}else{s=(int)(e-E);d=s;}
  float ex[HEADS];
  #pragma unroll
  for(int h=0;h<HEADS;h++){
    float v=g_as[s*HEADS+h]+g_ad[d*HEADS+h];
    v=(v>0.f)?v:0.2f*v;
    ex[h]=__expf(v);
    atomicAdd(&g_ssum[d*HEADS+h],ex[h]);}
  const float* xs=&g_x[(long)s*HEADS*C];
  float* go=&g_gout[(long)d*HEADS*C];
  #pragma unroll
  for(int h=0;h<HEADS;h++)
    #pragma unroll
    for(int c=0;c<C;c++)
      atomicAdd(&go[h*C+c],ex[h]*xs[h*C+c]);
  atomicAdd(&g_deg[s],1.f);
  atomicAdd(&g_nsum[d*C+g_lab[s]],1.f);
}

// ---------------- finalize ----------------
__global__ void k_final(const float* __restrict__ gb,float* __restrict__ out,int n){
  int i=blockIdx.x*blockDim.x+threadIdx.x;if(i>=n)return;
  float p[C],go[C];
  #pragma unroll
  for(int c=0;c<C;c++){p[c]=g_probs[i*C+c];go[c]=0.f;}
  #pragma unroll
  for(int h=0;h<HEADS;h++){
    float sh=g_ssum[i*HEADS+h]+1e-16f;float inv=1.f/sh;
    #pragma unroll
    for(int c=0;c<C;c++)go[c]+=g_gout[(long)i*HEADS*C+h*C+c]*inv;}
  float num=0.f,np=0.f,ng=0.f;
  #pragma unroll
  for(int c=0;c<C;c++){go[c]=go[c]*0.25f+gb[c];num+=p[c]*go[c];np+=p[c]*p[c];ng+=go[c]*go[c];}
  float den=fmaxf(sqrtf(np)*sqrtf(ng),1e-8f);
  float gconf=(num/den+1.f)*0.5f;
  float comb=0.4f*g_maxp[i]+0.2f*g_econf[i]+0.2f*g_tconf[i]+0.2f*gconf;
  int lab=g_lab[i];
  float navg=g_nsum[i*C+lab]/(g_deg[i]+1e-8f);
  float mask=((comb>0.85f)&&(navg>=0.6f))?1.f:0.f;
  out[i]=(float)lab;
  out[n+i]=comb;
  out[2*n+i]=mask;
  out[3*n+i]=g_maxp[i];
  out[4*n+i]=g_econf[i];
  out[5*n+i]=g_tconf[i];
  out[6*n+i]=gconf;
  out[7*n+i]=g_unc[i];
}

extern "C" void kernel_launch(void* const* d_in,const int* in_sizes,int n_in,
                              void* d_out,int out_size){
  const float* emb  =(const float*)d_in[0];
  const float* preds=(const float*)d_in[1];
  const int*   ei   =(const int*)  d_in[3];
  const float* cW1  =(const float*)d_in[4];
  const float* cb1  =(const float*)d_in[5];
  const float* cW2  =(const float*)d_in[6];
  const float* cb2  =(const float*)d_in[7];
  const float* w_ih0=(const float*)d_in[8];
  const float* w_hh0=(const float*)d_in[9];
  const float* b_ih0=(const float*)d_in[10];
  const float* b_hh0=(const float*)d_in[11];
  const float* w_ih1=(const float*)d_in[12];
  const float* w_hh1=(const float*)d_in[13];
  const float* b_ih1=(const float*)d_in[14];
  const float* b_hh1=(const float*)d_in[15];
  const float* gW   =(const float*)d_in[16];
  const float* gas  =(const float*)d_in[17];
  const float* gad  =(const float*)d_in[18];
  const float* gb   =(const float*)d_in[19];
  int n=in_sizes[1]/C;
  long E=in_sizes[3]/2;

  cudaFuncSetAttribute(k_lstm,cudaFuncAttributeMaxDynamicSharedMemorySize,23216*4);
  cudaFuncSetAttribute(k_conf,cudaFuncAttributeMaxDynamicSharedMemorySize,40960*4);

  k_prep<<<2048,256>>>(w_hh0,w_ih1,w_hh1,cW1,n);
  k_stage1<<<(n+255)/256,256>>>(preds,gW,gas,gad,n);
  k_conf<<<(n+31)/32,256,40960*4>>>(emb,cb1,cW2,cb2,n);
  k_lstm<<<(n+15)/16,256,23216*4>>>(preds,w_ih0,b_ih0,b_hh0,b_ih1,b_hh1,n);
  long tot=E+n;
  k_edge<<<(int)((tot+255)/256),256>>>(ei,E,n);
  k_final<<<(n+255)/256,256>>>(gb,(float*)d_out,n);
}

// round 5
// speedup vs baseline: 2.1008x; 1.0001x over previous
#include <cuda_runtime.h>
#include <math.h>

#define MAXN 100000
#define HID 256
#define C 10
#define LH 128
#define G4 512
#define TSTEPS 12
#define HEADS 4
#define KP 8           // k-steps per panel
#define PANEL_F 4096   // 512 gates * 8 k = floats per panel
#define NPAN 48        // 16 (layer1) + 32 (layer2)

__device__ float g_Wt1[LH*G4];      // 16 panels, layout [pp][half][g][4]
__device__ float g_Wt2[2*LH*G4];    // 32 panels, layout [pp][half][g][4]
__device__ float g_cW1t[HID*LH];
__device__ float g_probs[MAXN*C];
__device__ float g_x[MAXN*HEADS*C];
__device__ float g_as[MAXN*HEADS];
__device__ float g_ad[MAXN*HEADS];
__device__ float g_ssum[MAXN*HEADS];
__device__ float g_gout[MAXN*HEADS*C];
__device__ float g_deg[MAXN];
__device__ float g_nsum[MAXN*C];
__device__ float g_econf[MAXN];
__device__ float g_tconf[MAXN];
__device__ float g_maxp[MAXN];
__device__ float g_unc[MAXN];
__device__ int   g_lab[MAXN];

typedef unsigned long long u64;

__device__ __forceinline__ u64 fma2(u64 a,u64 b,u64 c){u64 d;asm("fma.rn.f32x2 %0,%1,%2,%3;":"=l"(d):"l"(a),"l"(b),"l"(c));return d;}
__device__ __forceinline__ u64 dup2(float x){u64 d;asm("mov.b64 %0,{%1,%1};":"=l"(d):"f"(x));return d;}
__device__ __forceinline__ float2 unp2(u64 v){float2 r;asm("mov.b64 {%0,%1},%2;":"=f"(r.x),"=f"(r.y):"l"(v));return r;}
__device__ __forceinline__ u64 pk2(float x,float y){u64 d;asm("mov.b64 %0,{%1,%2};":"=l"(d):"f"(x),"f"(y));return d;}
__device__ __forceinline__ void cpa16(float* s,const float* g){unsigned a=(unsigned)__cvta_generic_to_shared(s);asm volatile("cp.async.cg.shared.global [%0],[%1],16;"::"r"(a),"l"(g));}
__device__ __forceinline__ void cpcommit(){asm volatile("cp.async.commit_group;");}
__device__ __forceinline__ void cpwait(){asm volatile("cp.async.wait_group 0;");}
__device__ __forceinline__ float sigf(float x){return 1.f/(1.f+__expf(-x));}
__device__ __forceinline__ float tahf(float x){float e=__expf(2.f*x);return 1.f-2.f/(e+1.f);}

// ---------------- prep: panel-transposed weights + zero accumulators ----------------
__global__ void k_prep(const float* __restrict__ w_hh0,const float* __restrict__ w_ih1,
                       const float* __restrict__ w_hh1,const float* __restrict__ cW1,int n){
  long i=(long)blockIdx.x*blockDim.x+threadIdx.x; long st=(long)gridDim.x*blockDim.x;
  // layout: idx = ((pp*2+half)*512 + g)*4 + m ; k = pp*8 + half*4 + m
  for(long idx=i;idx<LH*G4;idx+=st){
    int m=(int)(idx&3); int g=(int)((idx>>2)&511); int ph=(int)(idx>>13);
    int k=(ph>>1)*8 + (ph&1)*4 + m;
    g_Wt1[idx]=w_hh0[g*LH+k];
  }
  for(long idx=i;idx<2*LH*G4;idx+=st){
    int m=(int)(idx&3); int g=(int)((idx>>2)&511); int ph=(int)(idx>>13);
    int k=(ph>>1)*8 + (ph&1)*4 + m;
    g_Wt2[idx]=(k<LH)?w_ih1[g*LH+k]:w_hh1[g*LH+k-LH];
  }
  for(long idx=i;idx<HID*LH;idx+=st){int k=(int)(idx/LH),o=(int)(idx%LH);g_cW1t[idx]=cW1[o*HID+k];}
  for(long idx=i;idx<(long)n*HEADS;idx+=st)g_ssum[idx]=0.f;
  for(long idx=i;idx<(long)n*HEADS*C;idx+=st)g_gout[idx]=0.f;
  for(long idx=i;idx<n;idx+=st)g_deg[idx]=0.f;
  for(long idx=i;idx<(long)n*C;idx+=st)g_nsum[idx]=0.f;
}

// ---------------- stage1: softmax/argmax/entropy + GAT projections ----------------
__global__ void k_stage1(const float* __restrict__ preds,const float* __restrict__ gW,
                         const float* __restrict__ gas,const float* __restrict__ gad,int n){
  __shared__ float sgW[C*HEADS*C],sas[HEADS*C],sad[HEADS*C];
  int t=threadIdx.x;
  for(int i=t;i<C*HEADS*C;i+=blockDim.x)sgW[i]=gW[i];
  if(t<HEADS*C){sas[t]=gas[t];sad[t]=gad[t];}
  __syncthreads();
  int i=blockIdx.x*blockDim.x+t; if(i>=n)return;
  float p[C];float m=-1e30f;
  #pragma unroll
  for(int c=0;c<C;c++){p[c]=preds[i*C+c];m=fmaxf(m,p[c]);}
  float s=0.f;
  #pragma unroll
  for(int c=0;c<C;c++){p[c]=expf(p[c]-m);s+=p[c];}
  float inv=1.f/s;int lab=0;float mp=-1.f,ent=0.f;
  #pragma unroll
  for(int c=0;c<C;c++){p[c]*=inv;if(p[c]>mp){mp=p[c];lab=c;}}
  #pragma unroll
  for(int c=0;c<C;c++){ent-=p[c]*logf(p[c]+1e-8f);g_probs[i*C+c]=p[c];}
  g_lab[i]=lab;g_maxp[i]=mp;g_unc[i]=ent/2.302585093f;
  float xv[HEADS*C];
  #pragma unroll
  for(int hc=0;hc<HEADS*C;hc++){float a=0.f;
    #pragma unroll
    for(int c=0;c<C;c++)a+=p[c]*sgW[c*(HEADS*C)+hc];
    xv[hc]=a;g_x[(long)i*(HEADS*C)+hc]=a;}
  #pragma unroll
  for(int h=0;h<HEADS;h++){float a=0.f,b=0.f;
    #pragma unroll
    for(int c=0;c<C;c++){a+=xv[h*C+c]*sas[h*C+c];b+=xv[h*C+c]*sad[h*C+c];}
    g_as[i*HEADS+h]=a;g_ad[i*HEADS+h]=b;}
}

// ---------------- confidence net: sigmoid(relu(emb@W1^T+b1)@W2^T+b2) ----------------
__global__ void __launch_bounds__(256) k_conf(const float* __restrict__ emb,const float* __restrict__ cb1,
                                              const float* __restrict__ cW2,const float* __restrict__ cb2,int n){
  extern __shared__ float sm[];
  float* sW=sm;          // 32768 floats (W1 transposed [k][128])
  float* sE=sm+32768;    // 8192 floats (emb [32][256])
  int t=threadIdx.x;int node0=blockIdx.x*32;
  for(int idx=t;idx<32768;idx+=256)sW[idx]=g_cW1t[idx];
  for(int idx=t;idx<8192;idx+=256){int nl=idx>>8,k=idx&255;sE[idx]=(node0+nl<n)?emb[(long)(node0+nl)*HID+k]:0.f;}
  __syncthreads();
  int j4=t&31,r=t>>5;
  float acc[4][4];
  #pragma unroll
  for(int a=0;a<4;a++){acc[a][0]=0;acc[a][1]=0;acc[a][2]=0;acc[a][3]=0;}
  for(int k=0;k<HID;k++){
    float4 w=*(const float4*)&sW[k*LH+j4*4];
    #pragma unroll
    for(int i=0;i<4;i++){
      float e=sE[(r*4+i)*HID+k];
      acc[i][0]=fmaf(e,w.x,acc[i][0]);acc[i][1]=fmaf(e,w.y,acc[i][1]);
      acc[i][2]=fmaf(e,w.z,acc[i][2]);acc[i][3]=fmaf(e,w.w,acc[i][3]);}}
  float b1[4],w2[4];
  #pragma unroll
  for(int cc=0;cc<4;cc++){b1[cc]=cb1[j4*4+cc];w2[cc]=cW2[j4*4+cc];}
  float b2=cb2[0];
  #pragma unroll
  for(int i=0;i<4;i++){
    float pi=0.f;
    #pragma unroll
    for(int cc=0;cc<4;cc++){float h=fmaxf(acc[i][cc]+b1[cc],0.f);pi=fmaf(h,w2[cc],pi);}
    #pragma unroll
    for(int off=16;off>0;off>>=1)pi+=__shfl_xor_sync(0xffffffffu,pi,off);
    if(j4==0){int node=node0+r*4+i;if(node<n)g_econf[node]=sigf(pi+b2);}
  }
}

// ---------------- fused 2-layer LSTM, 16 nodes/CTA, f32x2, 2 CTAs/SM ----------------
__device__ __forceinline__ const float* psrc(int q){
  return (q<16) ? (g_Wt1 + (long)q*PANEL_F) : (g_Wt2 + (long)(q-16)*PANEL_F);
}

__global__ void __launch_bounds__(256,2) k_lstm(const float* __restrict__ preds,const float* __restrict__ w_ih0,
    const float* __restrict__ b_ih0,const float* __restrict__ b_hh0,
    const float* __restrict__ b_ih1,const float* __restrict__ b_hh1,int n){
  extern __shared__ float sm[];
  float* panel=sm;          // 8192: 2 x 4096
  float* sXW=sm+8192;       // 8192: [8 pairs][512] f32x2
  float* sH1=sm+16384;      // 3072: [128][12] f32x2
  float* sH2=sm+19456;      // 3072
  float* sB2=sm+22528;      // 512
  float* sP =sm+23040;      // 160
  float* sRed=sm+23200;     // 16
  int t=threadIdx.x,j=t&127,ty=t>>7;
  int node0=blockIdx.x*16;
  for(int idx=t;idx<80;idx+=256){int pr=idx/10,c=idx%10;int n0=node0+pr*2;
    float x=(n0<n)?preds[n0*C+c]:0.f;float y=(n0+1<n)?preds[(n0+1)*C+c]:0.f;
    *(u64*)&sP[idx*2]=pk2(x,y);}
  for(int idx=t;idx<512;idx+=256)sB2[idx]=b_ih1[idx]+b_hh1[idx];
  for(int idx=t;idx<3072;idx+=256){sH1[idx]=0.f;sH2[idx]=0.f;}
  if(t<16)sRed[t]=0.f;
  __syncthreads();
  // xW_ih0 + biases, per node, once
  #pragma unroll
  for(int gi=0;gi<4;gi++){
    int g=gi*128+j;
    float wv[10];
    #pragma unroll
    for(int c=0;c<10;c++)wv[c]=w_ih0[g*10+c];
    float b0=b_ih0[g]+b_hh0[g];
    #pragma unroll
    for(int p=0;p<4;p++){
      int pair=ty*4+p;
      u64 a=dup2(b0);
      #pragma unroll
      for(int c=0;c<10;c++)a=fma2(*(const u64*)&sP[(pair*10+c)*2],dup2(wv[c]),a);
      *(u64*)&sXW[(pair*512+g)*2]=a;}}
  __syncthreads();

  u64 acc[4][4];
  float c1[8],c2[8],s1[8],s2[8];
  #pragma unroll
  for(int i=0;i<8;i++){c1[i]=0.f;c2[i]=0.f;s1[i]=0.f;s2[i]=0.f;}

  // prologue: prefetch panel 0
  {
    const float* src=psrc(0);
    #pragma unroll
    for(int i=0;i<4;i++){int u=t+i*256;cpa16(panel+u*4,src+u*4);}
    cpcommit();
  }

  for(int tt=0;tt<TSTEPS;tt++){
    // ---- layer 1 ----
    #pragma unroll
    for(int gi=0;gi<4;gi++)
      #pragma unroll
      for(int p=0;p<4;p++)acc[gi][p]=*(const u64*)&sXW[((ty*4+p)*512+gi*128+j)*2];
    for(int q=0;q<16;q++){
      cpwait();__syncthreads();
      {int nx=q+1;const float* src=psrc(nx);float* dst=panel+(nx&1)*PANEL_F;
       #pragma unroll
       for(int i=0;i<4;i++){int u=t+i*256;cpa16(dst+u*4,src+u*4);}
       cpcommit();}
      const float* sp=panel+(q&1)*PANEL_F;
      int kb=q*KP;
      #pragma unroll
      for(int half=0;half<2;half++){
        float4 w0=*(const float4*)&sp[(half*512+  0+j)*4];
        float4 w1=*(const float4*)&sp[(half*512+128+j)*4];
        float4 w2=*(const float4*)&sp[(half*512+256+j)*4];
        float4 w3=*(const float4*)&sp[(half*512+384+j)*4];
        const float* wp0=(const float*)&w0;const float* wp1=(const float*)&w1;
        const float* wp2=(const float*)&w2;const float* wp3=(const float*)&w3;
        #pragma unroll
        for(int kx=0;kx<4;kx++){
          int k=kb+half*4+kx;
          const u64* hp=(const u64*)&sH1[(k*12+ty*4)*2];
          u64 h0=hp[0],h1=hp[1],h2v=hp[2],h3=hp[3];
          u64 d0=dup2(wp0[kx]),d1=dup2(wp1[kx]),d2=dup2(wp2[kx]),d3=dup2(wp3[kx]);
          acc[0][0]=fma2(h0,d0,acc[0][0]);acc[0][1]=fma2(h1,d0,acc[0][1]);
          acc[0][2]=fma2(h2v,d0,acc[0][2]);acc[0][3]=fma2(h3,d0,acc[0][3]);
          acc[1][0]=fma2(h0,d1,acc[1][0]);acc[1][1]=fma2(h1,d1,acc[1][1]);
          acc[1][2]=fma2(h2v,d1,acc[1][2]);acc[1][3]=fma2(h3,d1,acc[1][3]);
          acc[2][0]=fma2(h0,d2,acc[2][0]);acc[2][1]=fma2(h1,d2,acc[2][1]);
          acc[2][2]=fma2(h2v,d2,acc[2][2]);acc[2][3]=fma2(h3,d2,acc[2][3]);
          acc[3][0]=fma2(h0,d3,acc[3][0]);acc[3][1]=fma2(h1,d3,acc[3][1]);
          acc[3][2]=fma2(h2v,d3,acc[3][2]);acc[3][3]=fma2(h3,d3,acc[3][3]);}}
    }
    __syncthreads();
    #pragma unroll
    for(int p=0;p<4;p++){
      float2 iv=unp2(acc[0][p]),fv=unp2(acc[1][p]),gv=unp2(acc[2][p]),ov=unp2(acc[3][p]);
      float cx=sigf(fv.x)*c1[p*2]+sigf(iv.x)*tahf(gv.x);
      float cy=sigf(fv.y)*c1[p*2+1]+sigf(iv.y)*tahf(gv.y);
      c1[p*2]=cx;c1[p*2+1]=cy;
      float hx=sigf(ov.x)*tahf(cx),hy=sigf(ov.y)*tahf(cy);
      int o=(j*12+ty*4+p)*2;sH1[o]=hx;sH1[o+1]=hy;}
    // ---- layer 2 ----
    #pragma unroll
    for(int gi=0;gi<4;gi++){u64 b=dup2(sB2[gi*128+j]);
      #pragma unroll
      for(int p=0;p<4;p++)acc[gi][p]=b;}
    for(int q=16;q<48;q++){
      cpwait();__syncthreads();
      {int nx=(q+1==48)?0:q+1;const float* src=psrc(nx);float* dst=panel+(nx&1)*PANEL_F;
       #pragma unroll
       for(int i=0;i<4;i++){int u=t+i*256;cpa16(dst+u*4,src+u*4);}
       cpcommit();}
      const float* sp=panel+(q&1)*PANEL_F;
      const float* hs=(q<32)?sH1:sH2;
      int kb=((q-16)*KP)&127;
      #pragma unroll
      for(int half=0;half<2;half++){
        float4 w0=*(const float4*)&sp[(half*512+  0+j)*4];
        float4 w1=*(const float4*)&sp[(half*512+128+j)*4];
        float4 w2=*(const float4*)&sp[(half*512+256+j)*4];
        float4 w3=*(const float4*)&sp[(half*512+384+j)*4];
        const float* wp0=(const float*)&w0;const float* wp1=(const float*)&w1;
        const float* wp2=(const float*)&w2;const float* wp3=(const float*)&w3;
        #pragma unroll
        for(int kx=0;kx<4;kx++){
          int k=kb+half*4+kx;
          const u64* hp=(const u64*)&hs[(k*12+ty*4)*2];
          u64 h0=hp[0],h1=hp[1],h2v=hp[2],h3=hp[3];
          u64 d0=dup2(wp0[kx]),d1=dup2(wp1[kx]),d2=dup2(wp2[kx]),d3=dup2(wp3[kx]);
          acc[0][0]=fma2(h0,d0,acc[0][0]);acc[0][1]=fma2(h1,d0,acc[0][1]);
          acc[0][2]=fma2(h2v,d0,acc[0][2]);acc[0][3]=fma2(h3,d0,acc[0][3]);
          acc[1][0]=fma2(h0,d1,acc[1][0]);acc[1][1]=fma2(h1,d1,acc[1][1]);
          acc[1][2]=fma2(h2v,d1,acc[1][2]);acc[1][3]=fma2(h3,d1,acc[1][3]);
          acc[2][0]=fma2(h0,d2,acc[2][0]);acc[2][1]=fma2(h1,d2,acc[2][1]);
          acc[2][2]=fma2(h2v,d2,acc[2][2]);acc[2][3]=fma2(h3,d2,acc[2][3]);
          acc[3][0]=fma2(h0,d3,acc[3][0]);acc[3][1]=fma2(h1,d3,acc[3][1]);
          acc[3][2]=fma2(h2v,d3,acc[3][2]);acc[3][3]=fma2(h3,d3,acc[3][3]);}}
    }
    __syncthreads();
    #pragma unroll
    for(int p=0;p<4;p++){
      float2 iv=unp2(acc[0][p]),fv=unp2(acc[1][p]),gv=unp2(acc[2][p]),ov=unp2(acc[3][p]);
      float cx=sigf(fv.x)*c2[p*2]+sigf(iv.x)*tahf(gv.x);
      float cy=sigf(fv.y)*c2[p*2+1]+sigf(iv.y)*tahf(gv.y);
      c2[p*2]=cx;c2[p*2+1]=cy;
      float hx=sigf(ov.x)*tahf(cx),hy=sigf(ov.y)*tahf(cy);
      int o=(j*12+ty*4+p)*2;sH2[o]=hx;sH2[o+1]=hy;
      s1[p*2]+=hx;s1[p*2+1]+=hy;s2[p*2]+=hx*hx;s2[p*2+1]+=hy*hy;}
  }
  __syncthreads();
  #pragma unroll
  for(int p=0;p<4;p++){
    #pragma unroll
    for(int cc=0;cc<2;cc++){
      float a=s1[p*2+cc],b=s2[p*2+cc];
      float var=(b-a*a*(1.f/12.f))*(1.f/11.f);
      atomicAdd(&sRed[(ty*4+p)*2+cc],var);}}
  __syncthreads();
  if(t<16){int node=node0+t;if(node<n)g_tconf[node]=1.f/(1.f+sRed[t]*(1.f/128.f));}
}

// ---------------- single-pass GAT edge scatter + agreement scatter ----------------
__global__ void k_edge(const int* __restrict__ ei,long E,int n){
  long e=(long)blockIdx.x*blockDim.x+threadIdx.x;
  long tot=E+n;
  if(e>=tot)return;
  int s,d;
  if(e<E){s=ei[e];d=ei[E+e];}else{s=(int)(e-E);d=s;}
  float ex[HEADS];
  #pragma unroll
  for(int h=0;h<HEADS;h++){
    float v=g_as[s*HEADS+h]+g_ad[d*HEADS+h];
    v=(v>0.f)?v:0.2f*v;
    ex[h]=__expf(v);
    atomicAdd(&g_ssum[d*HEADS+h],ex[h]);}
  const float* xs=&g_x[(long)s*HEADS*C];
  float* go=&g_gout[(long)d*HEADS*C];
  #pragma unroll
  for(int h=0;h<HEADS;h++)
    #pragma unroll
    for(int c=0;c<C;c++)
      atomicAdd(&go[h*C+c],ex[h]*xs[h*C+c]);
  atomicAdd(&g_deg[s],1.f);
  atomicAdd(&g_nsum[d*C+g_lab[s]],1.f);
}

// ---------------- finalize ----------------
__global__ void k_final(const float* __restrict__ gb,float* __restrict__ out,int n){
  int i=blockIdx.x*blockDim.x+threadIdx.x;if(i>=n)return;
  float p[C],go[C];
  #pragma unroll
  for(int c=0;c<C;c++){p[c]=g_probs[i*C+c];go[c]=0.f;}
  #pragma unroll
  for(int h=0;h<HEADS;h++){
    float sh=g_ssum[i*HEADS+h]+1e-16f;float inv=1.f/sh;
    #pragma unroll
    for(int c=0;c<C;c++)go[c]+=g_gout[(long)i*HEADS*C+h*C+c]*inv;}
  float num=0.f,np=0.f,ng=0.f;
  #pragma unroll
  for(int c=0;c<C;c++){go[c]=go[c]*0.25f+gb[c];num+=p[c]*go[c];np+=p[c]*p[c];ng+=go[c]*go[c];}
  float den=fmaxf(sqrtf(np)*sqrtf(ng),1e-8f);
  float gconf=(num/den+1.f)*0.5f;
  float comb=0.4f*g_maxp[i]+0.2f*g_econf[i]+0.2f*g_tconf[i]+0.2f*gconf;
  int lab=g_lab[i];
  float navg=g_nsum[i*C+lab]/(g_deg[i]+1e-8f);
  float mask=((comb>0.85f)&&(navg>=0.6f))?1.f:0.f;
  out[i]=(float)lab;
  out[n+i]=comb;
  out[2*n+i]=mask;
  out[3*n+i]=g_maxp[i];
  out[4*n+i]=g_econf[i];
  out[5*n+i]=g_tconf[i];
  out[6*n+i]=gconf;
  out[7*n+i]=g_unc[i];
}

extern "C" void kernel_launch(void* const* d_in,const int* in_sizes,int n_in,
                              void* d_out,int out_size){
  const float* emb  =(const float*)d_in[0];
  const float* preds=(const float*)d_in[1];
  const int*   ei   =(const int*)  d_in[3];
  const float* cW1  =(const float*)d_in[4];
  const float* cb1  =(const float*)d_in[5];
  const float* cW2  =(const float*)d_in[6];
  const float* cb2  =(const float*)d_in[7];
  const float* w_ih0=(const float*)d_in[8];
  const float* w_hh0=(const float*)d_in[9];
  const float* b_ih0=(const float*)d_in[10];
  const float* b_hh0=(const float*)d_in[11];
  const float* w_ih1=(const float*)d_in[12];
  const float* w_hh1=(const float*)d_in[13];
  const float* b_ih1=(const float*)d_in[14];
  const float* b_hh1=(const float*)d_in[15];
  const float* gW   =(const float*)d_in[16];
  const float* gas  =(const float*)d_in[17];
  const float* gad  =(const float*)d_in[18];
  const float* gb   =(const float*)d_in[19];
  int n=in_sizes[1]/C;
  long E=in_sizes[3]/2;

  cudaFuncSetAttribute(k_lstm,cudaFuncAttributeMaxDynamicSharedMemorySize,23216*4);
  cudaFuncSetAttribute(k_conf,cudaFuncAttributeMaxDynamicSharedMemorySize,40960*4);

  k_prep<<<2048,256>>>(w_hh0,w_ih1,w_hh1,cW1,n);
  k_stage1<<<(n+255)/256,256>>>(preds,gW,gas,gad,n);
  k_conf<<<(n+31)/32,256,40960*4>>>(emb,cb1,cW2,cb2,n);
  k_lstm<<<(n+15)/16,256,23216*4>>>(preds,w_ih0,b_ih0,b_hh0,b_ih1,b_hh1,n);
  long tot=E+n;
  k_edge<<<(int)((tot+255)/256),256>>>(ei,E,n);
  k_final<<<(n+255)/256,256>>>(gb,(float*)d_out,n);
}

// round 7
// speedup vs baseline: 7.5935x; 3.6145x over previous
#include <cuda_runtime.h>
#include <cuda_bf16.h>
#include <math.h>

#define MAXN 100000
#define HID 256
#define C 10
#define HEADS 4
#define TSTEPS 12

extern __shared__ char smem_dyn[];

__device__ unsigned g_wx[4096];
__device__ unsigned g_w1[8*4096];
__device__ unsigned g_w2[16*4096];
__device__ float g_cW1t[HID*128];
__device__ float g_probs[MAXN*C];
__device__ float g_x[MAXN*HEADS*C];
__device__ float g_as[MAXN*HEADS];
__device__ float g_ad[MAXN*HEADS];
__device__ float g_ssum[MAXN*HEADS];
__device__ float g_gout[MAXN*HEADS*C];
__device__ float g_deg[MAXN];
__device__ float g_nsum[MAXN*C];
__device__ float g_econf[MAXN];
__device__ float g_tconf[MAXN];
__device__ float g_maxp[MAXN];
__device__ float g_unc[MAXN];
__device__ int   g_lab[MAXN];

__device__ __forceinline__ unsigned pkbf(float a,float b){
  return (unsigned)__bfloat16_as_ushort(__float2bfloat16(a))
       |((unsigned)__bfloat16_as_ushort(__float2bfloat16(b))<<16);}
__device__ __forceinline__ float tap(float x){float y;asm("tanh.approx.f32 %0,%1;":"=f"(y):"f"(x));return y;}
__device__ __forceinline__ float sgm(float x){return 0.5f*tap(0.5f*x)+0.5f;}
__device__ __forceinline__ void cpa16(char* s,const char* g){unsigned a=(unsigned)__cvta_generic_to_shared(s);asm volatile("cp.async.cg.shared.global [%0],[%1],16;"::"r"(a),"l"(g));}
__device__ __forceinline__ void cpcommit(){asm volatile("cp.async.commit_group;");}
__device__ __forceinline__ void cpwait(){asm volatile("cp.async.wait_group 0;");}
#define MMA(d,a,b0,b1) asm volatile("mma.sync.aligned.m16n8k16.row.col.f32.bf16.bf16.f32 {%0,%1,%2,%3},{%4,%5,%6,%7},{%8,%9},{%0,%1,%2,%3};":"+f"(d[0]),"+f"(d[1]),"+f"(d[2]),"+f"(d[3]):"r"(a[0]),"r"(a[1]),"r"(a[2]),"r"(a[3]),"r"(b0),"r"(b1))

// ---------------- prep: frag-packed bf16 weights + transposes + zeros ----------------
__global__ void k_prep(const float* __restrict__ w_ih0,const float* __restrict__ w_hh0,
                       const float* __restrict__ w_ih1,const float* __restrict__ w_hh1,
                       const float* __restrict__ cW1,int n){
  long i=(long)blockIdx.x*blockDim.x+threadIdx.x; long st=(long)gridDim.x*blockDim.x;
  for(long idx=i;idx<4096;idx+=st){
    int reg=(int)idx&1,lane=((int)idx>>1)&31,nt=(int)idx>>6;
    int nn=nt*8+(lane>>2),k0=(lane&3)*2+reg*8;
    float lo=(k0<C)?w_ih0[nn*C+k0]:0.f,hi=(k0+1<C)?w_ih0[nn*C+k0+1]:0.f;
    g_wx[idx]=pkbf(lo,hi);}
  for(long idx=i;idx<8*4096;idx+=st){
    int kc=(int)idx>>12,r=(int)idx&4095,reg=r&1,lane=(r>>1)&31,nt=r>>6;
    int nn=nt*8+(lane>>2),k0=kc*16+(lane&3)*2+reg*8;
    g_w1[idx]=pkbf(w_hh0[nn*128+k0],w_hh0[nn*128+k0+1]);}
  for(long idx=i;idx<16*4096;idx+=st){
    int kc=(int)idx>>12,r=(int)idx&4095,reg=r&1,lane=(r>>1)&31,nt=r>>6;
    int nn=nt*8+(lane>>2),k0=kc*16+(lane&3)*2+reg*8;
    float lo=(k0<128)?w_ih1[nn*128+k0]:w_hh1[nn*128+k0-128];
    float hi=(k0<128)?w_ih1[nn*128+k0+1]:w_hh1[nn*128+k0-127];
    g_w2[idx]=pkbf(lo,hi);}
  for(long idx=i;idx<HID*128;idx+=st){int k=(int)(idx/128),o=(int)(idx%128);g_cW1t[idx]=cW1[o*HID+k];}
  for(long idx=i;idx<(long)n*HEADS;idx+=st)g_ssum[idx]=0.f;
  for(long idx=i;idx<(long)n*HEADS*C;idx+=st)g_gout[idx]=0.f;
  for(long idx=i;idx<n;idx+=st)g_deg[idx]=0.f;
  for(long idx=i;idx<(long)n*C;idx+=st)g_nsum[idx]=0.f;
}

// ---------------- stage1 ----------------
__global__ void k_stage1(const float* __restrict__ preds,const float* __restrict__ gW,
                         const float* __restrict__ gas,const float* __restrict__ gad,int n){
  __shared__ float sgW[C*HEADS*C],sas[HEADS*C],sad[HEADS*C];
  int t=threadIdx.x;
  for(int i=t;i<C*HEADS*C;i+=blockDim.x)sgW[i]=gW[i];
  if(t<HEADS*C){sas[t]=gas[t];sad[t]=gad[t];}
  __syncthreads();
  int i=blockIdx.x*blockDim.x+t; if(i>=n)return;
  float p[C];float m=-1e30f;
  #pragma unroll
  for(int c=0;c<C;c++){p[c]=preds[i*C+c];m=fmaxf(m,p[c]);}
  float s=0.f;
  #pragma unroll
  for(int c=0;c<C;c++){p[c]=expf(p[c]-m);s+=p[c];}
  float inv=1.f/s;int lab=0;float mp=-1.f,ent=0.f;
  #pragma unroll
  for(int c=0;c<C;c++){p[c]*=inv;if(p[c]>mp){mp=p[c];lab=c;}}
  #pragma unroll
  for(int c=0;c<C;c++){ent-=p[c]*logf(p[c]+1e-8f);g_probs[i*C+c]=p[c];}
  g_lab[i]=lab;g_maxp[i]=mp;g_unc[i]=ent/2.302585093f;
  float xv[HEADS*C];
  #pragma unroll
  for(int hc=0;hc<HEADS*C;hc++){float a=0.f;
    #pragma unroll
    for(int c=0;c<C;c++)a+=p[c]*sgW[c*(HEADS*C)+hc];
    xv[hc]=a;g_x[(long)i*(HEADS*C)+hc]=a;}
  #pragma unroll
  for(int h=0;h<HEADS;h++){float a=0.f,b=0.f;
    #pragma unroll
    for(int c=0;c<C;c++){a+=xv[h*C+c]*sas[h*C+c];b+=xv[h*C+c]*sad[h*C+c];}
    g_as[i*HEADS+h]=a;g_ad[i*HEADS+h]=b;}
}

// ---------------- confidence net ----------------
__global__ void __launch_bounds__(256) k_conf(const float* __restrict__ emb,const float* __restrict__ cb1,
                                              const float* __restrict__ cW2,const float* __restrict__ cb2,int n){
  float* sW=(float*)smem_dyn; float* sE=sW+32768;
  int t=threadIdx.x;int node0=blockIdx.x*32;
  for(int idx=t;idx<32768;idx+=256)sW[idx]=g_cW1t[idx];
  for(int idx=t;idx<8192;idx+=256){int nl=idx>>8,k=idx&255;sE[idx]=(node0+nl<n)?emb[(long)(node0+nl)*HID+k]:0.f;}
  __syncthreads();
  int j4=t&31,r=t>>5;
  float acc[4][4];
  #pragma unroll
  for(int a=0;a<4;a++){acc[a][0]=0;acc[a][1]=0;acc[a][2]=0;acc[a][3]=0;}
  for(int k=0;k<HID;k++){
    float4 w=*(const float4*)&sW[k*128+j4*4];
    #pragma unroll
    for(int i=0;i<4;i++){
      float e=sE[(r*4+i)*HID+k];
      acc[i][0]=fmaf(e,w.x,acc[i][0]);acc[i][1]=fmaf(e,w.y,acc[i][1]);
      acc[i][2]=fmaf(e,w.z,acc[i][2]);acc[i][3]=fmaf(e,w.w,acc[i][3]);}}
  float b1[4],w2[4];
  #pragma unroll
  for(int cc=0;cc<4;cc++){b1[cc]=cb1[j4*4+cc];w2[cc]=cW2[j4*4+cc];}
  float b2=cb2[0];
  #pragma unroll
  for(int i=0;i<4;i++){
    float pi=0.f;
    #pragma unroll
    for(int cc=0;cc<4;cc++){float h=fmaxf(acc[i][cc]+b1[cc],0.f);pi=fmaf(h,w2[cc],pi);}
    #pragma unroll
    for(int off=16;off>0;off>>=1)pi+=__shfl_xor_sync(0xffffffffu,pi,off);
    if(j4==0){int node=node0+r*4+i;if(node<n)g_econf[node]=1.f/(1.f+__expf(-(pi+b2)));}
  }
}

// ---------------- LSTM: bf16 mma.sync, 64 nodes/CTA, 512 thr ----------------
__device__ __forceinline__ void chunk(float acc[4][4][4],const __nv_bfloat16* A,int kb,
                                      const unsigned* pan,int w,int gid,int tg,int lane){
  unsigned af[4][4];
  const char* p=(const char*)A;
  #pragma unroll
  for(int mt=0;mt<4;mt++){int r=mt*16+gid;int cb=kb+tg*2;
    af[mt][0]=*(const unsigned*)(p+(r*264+cb)*2);
    af[mt][1]=*(const unsigned*)(p+((r+8)*264+cb)*2);
    af[mt][2]=*(const unsigned*)(p+(r*264+cb+8)*2);
    af[mt][3]=*(const unsigned*)(p+((r+8)*264+cb+8)*2);}
  #pragma unroll
  for(int g=0;g<4;g++){
    const unsigned* bp=&pan[((g*16+w)*32+lane)*2];
    unsigned b0=bp[0],b1=bp[1];
    #pragma unroll
    for(int mt=0;mt<4;mt++)MMA(acc[mt][g],af[mt],b0,b1);}
}

__global__ void __launch_bounds__(512,1) k_lstm(const float* __restrict__ preds,
    const float* __restrict__ b_ih0,const float* __restrict__ b_hh0,
    const float* __restrict__ b_ih1,const float* __restrict__ b_hh1,int n){
  char* sm=smem_dyn;
  unsigned* pan0=(unsigned*)sm; unsigned* pan1=(unsigned*)(sm+16384);
  unsigned* sWX=(unsigned*)(sm+32768);
  __nv_bfloat16* sH=(__nv_bfloat16*)(sm+49152);   // [64][264], h1=cols0..127, h2=128..255
  __nv_bfloat16* sX=(__nv_bfloat16*)(sm+82944);   // [64][24]
  float* sB1=(float*)(sm+86016);
  float* sB2=(float*)(sm+88064);
  float* sVar=(float*)(sm+90112);                 // [2][16][512]
  float* sRed=(float*)(sm+155648);
  int t=threadIdx.x,w=t>>5,lane=t&31,gid=lane>>2,tg=lane&3;
  int node0=blockIdx.x*64;
  for(int idx=t;idx<1024;idx+=512){int r=idx>>4,c2=idx&15;
    sX[r*24+c2]=__float2bfloat16((c2<C&&node0+r<n)?preds[(long)(node0+r)*C+c2]:0.f);}
  for(int idx=t;idx<4096;idx+=512)sWX[idx]=g_wx[idx];
  sB1[t]=b_ih0[t]+b_hh0[t]; sB2[t]=b_ih1[t]+b_hh1[t];
  for(int idx=t;idx<8448;idx+=512)((unsigned*)sH)[idx]=0;
  if(t<64)sRed[t]=0.f;
  __syncthreads();
  float cst1[16],cst2[16];
  #pragma unroll
  for(int i=0;i<16;i++){cst1[i]=0.f;cst2[i]=0.f;}
  cpa16((char*)pan0+t*16,(const char*)g_w1+t*16);
  cpa16((char*)pan0+(t+512)*16,(const char*)g_w1+(t+512)*16);
  cpcommit();
  float acc[4][4][4];
  for(int tt=0;tt<TSTEPS;tt++){
    // ---- layer1: bias init + x-chunk + 8 streamed chunks ----
    #pragma unroll
    for(int g=0;g<4;g++){int nb=g*128+w*8+tg*2;float b0=sB1[nb],b1=sB1[nb+1];
      #pragma unroll
      for(int mt=0;mt<4;mt++){acc[mt][g][0]=b0;acc[mt][g][1]=b1;acc[mt][g][2]=b0;acc[mt][g][3]=b1;}}
    {
      unsigned af[4][4];const char* p=(const char*)sX;
      #pragma unroll
      for(int mt=0;mt<4;mt++){int r=mt*16+gid;int cb=tg*2;
        af[mt][0]=*(const unsigned*)(p+(r*24+cb)*2);
        af[mt][1]=*(const unsigned*)(p+((r+8)*24+cb)*2);
        af[mt][2]=*(const unsigned*)(p+(r*24+cb+8)*2);
        af[mt][3]=*(const unsigned*)(p+((r+8)*24+cb+8)*2);}
      #pragma unroll
      for(int g=0;g<4;g++){
        const unsigned* bp=&sWX[((g*16+w)*32+lane)*2];
        unsigned b0=bp[0],b1=bp[1];
        #pragma unroll
        for(int mt=0;mt<4;mt++)MMA(acc[mt][g],af[mt],b0,b1);}
    }
    for(int q=0;q<8;q++){
      cpwait();__syncthreads();
      {int nx=q+1;
       const char* src=(nx<8)?(const char*)(g_w1+nx*4096):(const char*)(g_w2+(nx-8)*4096);
       char* dst=(char*)((nx&1)?pan1:pan0);
       cpa16(dst+t*16,src+t*16);cpa16(dst+(t+512)*16,src+(t+512)*16);cpcommit();}
      chunk(acc,sH,q*16,(q&1)?pan1:pan0,w,gid,tg,lane);
    }
    __syncthreads();
    #pragma unroll
    for(int mt=0;mt<4;mt++){
      float h[4];
      #pragma unroll
      for(int q=0;q<4;q++){
        float iv=acc[mt][0][q],fv=acc[mt][1][q],gv=acc[mt][2][q],ov=acc[mt][3][q];
        float cc=sgm(fv)*cst1[mt*4+q]+sgm(iv)*tap(gv);
        cst1[mt*4+q]=cc; h[q]=sgm(ov)*tap(cc);}
      int r1=mt*16+gid,j=w*8+tg*2;
      *(unsigned*)&sH[r1*264+j]=pkbf(h[0],h[1]);
      *(unsigned*)&sH[(r1+8)*264+j]=pkbf(h[2],h[3]);
    }
    // ---- layer2: 16 streamed chunks over [h1|h2] ----
    #pragma unroll
    for(int g=0;g<4;g++){int nb=g*128+w*8+tg*2;float b0=sB2[nb],b1=sB2[nb+1];
      #pragma unroll
      for(int mt=0;mt<4;mt++){acc[mt][g][0]=b0;acc[mt][g][1]=b1;acc[mt][g][2]=b0;acc[mt][g][3]=b1;}}
    for(int q=8;q<24;q++){
      cpwait();__syncthreads();
      if(!(tt==TSTEPS-1&&q==23)){
       int nx=(q+1)%24;
       const char* src=(nx<8)?(const char*)(g_w1+nx*4096):(const char*)(g_w2+(nx-8)*4096);
       char* dst=(char*)((nx&1)?pan1:pan0);
       cpa16(dst+t*16,src+t*16);cpa16(dst+(t+512)*16,src+(t+512)*16);cpcommit();}
      chunk(acc,sH,(q-8)*16,(q&1)?pan1:pan0,w,gid,tg,lane);
    }
    __syncthreads();
    #pragma unroll
    for(int mt=0;mt<4;mt++){
      float h[4];
      #pragma unroll
      for(int q=0;q<4;q++){
        float iv=acc[mt][0][q],fv=acc[mt][1][q],gv=acc[mt][2][q],ov=acc[mt][3][q];
        float cc=sgm(fv)*cst2[mt*4+q]+sgm(iv)*tap(gv);
        cst2[mt*4+q]=cc; h[q]=sgm(ov)*tap(cc);}
      int r1=mt*16+gid,j=128+w*8+tg*2;
      *(unsigned*)&sH[r1*264+j]=pkbf(h[0],h[1]);
      *(unsigned*)&sH[(r1+8)*264+j]=pkbf(h[2],h[3]);
      #pragma unroll
      for(int q=0;q<4;q++){
        int s=mt*4+q;float hv=h[q];
        if(tt==0){sVar[s*512+t]=hv;sVar[8192+s*512+t]=hv*hv;}
        else{sVar[s*512+t]+=hv;sVar[8192+s*512+t]+=hv*hv;}}
    }
  }
  __syncthreads();
  #pragma unroll
  for(int mt=0;mt<4;mt++)
    #pragma unroll
    for(int q=0;q<4;q++){
      int s=mt*4+q;
      float a=sVar[s*512+t],b=sVar[8192+s*512+t];
      float var=(b-a*a*(1.f/12.f))*(1.f/11.f);
      atomicAdd(&sRed[mt*16+gid+((q>=2)?8:0)],var);}
  __syncthreads();
  if(t<64){int node=node0+t;if(node<n)g_tconf[node]=1.f/(1.f+sRed[t]*(1.f/128.f));}
}

// ---------------- GAT edge + agreement scatter ----------------
__global__ void k_edge(const int* __restrict__ ei,long E,int n){
  long e=(long)blockIdx.x*blockDim.x+threadIdx.x;
  long tot=E+n; if(e>=tot)return;
  int s,d;
  if(e<E){s=ei[e];d=ei[E+e];}else{s=(int)(e-E);d=s;}
  float ex[HEADS];
  #pragma unroll
  for(int h=0;h<HEADS;h++){
    float v=g_as[s*HEADS+h]+g_ad[d*HEADS+h];
    v=(v>0.f)?v:0.2f*v;
    ex[h]=__expf(v);
    atomicAdd(&g_ssum[d*HEADS+h],ex[h]);}
  const float* xs=&g_x[(long)s*HEADS*C];
  float* go=&g_gout[(long)d*HEADS*C];
  #pragma unroll
  for(int h=0;h<HEADS;h++)
    #pragma unroll
    for(int c=0;c<C;c++)
      atomicAdd(&go[h*C+c],ex[h]*xs[h*C+c]);
  atomicAdd(&g_deg[s],1.f);
  atomicAdd(&g_nsum[d*C+g_lab[s]],1.f);
}

// ---------------- finalize ----------------
__global__ void k_final(const float* __restrict__ gb,float* __restrict__ out,int n){
  int i=blockIdx.x*blockDim.x+threadIdx.x;if(i>=n)return;
  float p[C],go[C];
  #pragma unroll
  for(int c=0;c<C;c++){p[c]=g_probs[i*C+c];go[c]=0.f;}
  #pragma unroll
  for(int h=0;h<HEADS;h++){
    float sh=g_ssum[i*HEADS+h]+1e-16f;float inv=1.f/sh;
    #pragma unroll
    for(int c=0;c<C;c++)go[c]+=g_gout[(long)i*HEADS*C+h*C+c]*inv;}
  float num=0.f,np=0.f,ng=0.f;
  #pragma unroll
  for(int c=0;c<C;c++){go[c]=go[c]*0.25f+gb[c];num+=p[c]*go[c];np+=p[c]*p[c];ng+=go[c]*go[c];}
  float den=fmaxf(sqrtf(np)*sqrtf(ng),1e-8f);
  float gconf=(num/den+1.f)*0.5f;
  float comb=0.4f*g_maxp[i]+0.2f*g_econf[i]+0.2f*g_tconf[i]+0.2f*gconf;
  int lab=g_lab[i];
  float navg=g_nsum[i*C+lab]/(g_deg[i]+1e-8f);
  float mask=((comb>0.85f)&&(navg>=0.6f))?1.f:0.f;
  out[i]=(float)lab; out[n+i]=comb; out[2*n+i]=mask; out[3*n+i]=g_maxp[i];
  out[4*n+i]=g_econf[i]; out[5*n+i]=g_tconf[i]; out[6*n+i]=gconf; out[7*n+i]=g_unc[i];
}

extern "C" void kernel_launch(void* const* d_in,const int* in_sizes,int n_in,
                              void* d_out,int out_size){
  const float* emb  =(const float*)d_in[0];
  const float* preds=(const float*)d_in[1];
  const int*   ei   =(const int*)  d_in[3];
  const float* cW1  =(const float*)d_in[4];
  const float* cb1  =(const float*)d_in[5];
  const float* cW2  =(const float*)d_in[6];
  const float* cb2  =(const float*)d_in[7];
  const float* w_ih0=(const float*)d_in[8];
  const float* w_hh0=(const float*)d_in[9];
  const float* b_ih0=(const float*)d_in[10];
  const float* b_hh0=(const float*)d_in[11];
  const float* w_ih1=(const float*)d_in[12];
  const float* w_hh1=(const float*)d_in[13];
  const float* b_ih1=(const float*)d_in[14];
  const float* b_hh1=(const float*)d_in[15];
  const float* gW   =(const float*)d_in[16];
  const float* gas  =(const float*)d_in[17];
  const float* gad  =(const float*)d_in[18];
  const float* gb   =(const float*)d_in[19];
  int n=in_sizes[1]/C;
  long E=in_sizes[3]/2;

  cudaFuncSetAttribute(k_lstm,cudaFuncAttributeMaxDynamicSharedMemorySize,155904);
  cudaFuncSetAttribute(k_conf,cudaFuncAttributeMaxDynamicSharedMemorySize,40960*4);

  k_prep<<<2048,256>>>(w_ih0,w_hh0,w_ih1,w_hh1,cW1,n);
  k_stage1<<<(n+255)/256,256>>>(preds,gW,gas,gad,n);
  k_conf<<<(n+31)/32,256,40960*4>>>(emb,cb1,cW2,cb2,n);
  k_lstm<<<(n+63)/64,512,155904>>>(preds,b_ih0,b_hh0,b_ih1,b_hh1,n);
  long tot=E+n;
  k_edge<<<(int)((tot+255)/256),256>>>(ei,E,n);
  k_final<<<(n+255)/256,256>>>(gb,(float*)d_out,n);
}